// round 1
// baseline (speedup 1.0000x reference)
#include <cuda_runtime.h>

#define NCLS 21
#define NB 8
#define HW (512*512)
#define PPB 2048        // pixels per block
#define TPB 256         // threads per block
#define BLOCKS_PER_IMG (HW / PPB)   // 128
#define EPS 1e-10f

// Global accumulators (no cudaMalloc allowed). Zeroed each launch by zero_kernel.
__device__ float g_inter[NB * NCLS];
__device__ float g_aout [NB * NCLS];
__device__ float g_atgt [NB * NCLS];
__device__ float g_T    [NCLS];

__global__ void zero_kernel() {
    int i = threadIdx.x;
    if (i < NB * NCLS) { g_inter[i] = 0.f; g_aout[i] = 0.f; g_atgt[i] = 0.f; }
    if (i < NCLS)        g_T[i] = 0.f;
}

__global__ __launch_bounds__(TPB) void hist_kernel(const float* __restrict__ pr,
                                                   const int*   __restrict__ gt) {
    __shared__ float s_inter[NCLS];
    __shared__ float s_aout [NCLS];
    __shared__ float s_atgt [NCLS];
    __shared__ float s_T    [NCLS];

    const int tid = threadIdx.x;
    if (tid < NCLS) { s_inter[tid] = 0.f; s_aout[tid] = 0.f; s_atgt[tid] = 0.f; s_T[tid] = 0.f; }
    __syncthreads();

    const int b     = blockIdx.x / BLOCKS_PER_IMG;
    const int chunk = blockIdx.x % BLOCKS_PER_IMG;
    const float* __restrict__ base  = pr + (size_t)b * NCLS * HW;
    const int*   __restrict__ gbase = gt + (size_t)b * HW;

    #pragma unroll 1
    for (int i = 0; i < PPB / TPB; ++i) {
        const int pix = chunk * PPB + i * TPB + tid;
        const int g   = gbase[pix];
        const float* __restrict__ p = base + pix;

        float vals[NCLS];
        float m = -3.0e38f;
        int   am = 0;
        float vgt = 0.f;
        #pragma unroll
        for (int k = 0; k < NCLS; ++k) {
            float v = p[(size_t)k * HW];
            vals[k] = v;
            if (v > m) { m = v; am = k; }   // strict > : first max wins (matches jnp.argmax)
            if (k == g) vgt = v;
        }
        float se = 0.f;
        #pragma unroll
        for (int k = 0; k < NCLS; ++k) se += __expf(vals[k] - m);
        const float logp = vgt - m - __logf(se);

        atomicAdd(&s_atgt[g], 1.f);
        atomicAdd(&s_aout[am], 1.f);
        if (am == g) atomicAdd(&s_inter[g], 1.f);
        atomicAdd(&s_T[g], logp);
    }
    __syncthreads();

    if (tid < NCLS) {
        atomicAdd(&g_inter[b * NCLS + tid], s_inter[tid]);
        atomicAdd(&g_aout [b * NCLS + tid], s_aout [tid]);
        atomicAdd(&g_atgt [b * NCLS + tid], s_atgt [tid]);
        atomicAdd(&g_T    [tid],            s_T    [tid]);
    }
}

__global__ void finalize_kernel(float* __restrict__ out) {
    const int k = threadIdx.x;   // one warp
    float w = 0.f, T = 0.f, N = 0.f;
    if (k < NCLS) {
        float dice = 0.f;
        #pragma unroll
        for (int b = 0; b < NB; ++b) {
            const float I  = g_inter[b * NCLS + k];
            const float Ao = g_aout [b * NCLS + k];
            const float At = g_atgt [b * NCLS + k];
            dice += 2.f * I / (Ao + At + EPS);
            N += At;
        }
        w = 1.f - dice * (1.f / 8.f);   // weight[k]
        T = g_T[k];
    }
    float wsum = w, wT = w * T, wN = w * N;
    #pragma unroll
    for (int o = 16; o > 0; o >>= 1) {
        wsum += __shfl_down_sync(0xffffffffu, wsum, o);
        wT   += __shfl_down_sync(0xffffffffu, wT,   o);
        wN   += __shfl_down_sync(0xffffffffu, wN,   o);
    }
    if (k == 0) {
        // out = mean(weight) + celoss,  celoss = -(sum w*T)/(sum w*N)
        out[0] = wsum * (1.f / 21.f) - wT / wN;
    }
}

extern "C" void kernel_launch(void* const* d_in, const int* in_sizes, int n_in,
                              void* d_out, int out_size) {
    // pr: 8*21*512*512 = 44040192 elems; gt: 8*512*512 = 2097152 elems.
    const float* pr;
    const int*   gt;
    if (in_sizes[0] > in_sizes[1]) {
        pr = (const float*)d_in[0];
        gt = (const int*)  d_in[1];
    } else {
        pr = (const float*)d_in[1];
        gt = (const int*)  d_in[0];
    }
    float* out = (float*)d_out;

    zero_kernel    <<<1, 256>>>();
    hist_kernel    <<<NB * BLOCKS_PER_IMG, TPB>>>(pr, gt);
    finalize_kernel<<<1, 32>>>(out);
}